// round 15
// baseline (speedup 1.0000x reference)
#include <cuda_runtime.h>
#include <cuda_fp16.h>
#include <cstdint>

#define BB 4
#define CI 256
#define CO 256
#define HH 64
#define WW 64
#define HW 4096
#define KD 2304          // CI * 9
#define MTOT 16384
#define NCHUNK 72        // KD / 32  (B packing granularity)
#define NKT2 36          // KD / 64  (gemm main-loop chunks)
#define PP 4356          // 66*66 padded pixels

// ---------------- scratch ----------------
__device__ __align__(16) uint32_t g_wB[NCHUNK * 4096];     // frag-ordered fp16 B (main, tap-major k)
__device__ __align__(16) uint32_t g_wOffB[NCHUNK * 384];   // frag-ordered fp16 B (offset)
__device__ __align__(16) __half g_A[(size_t)MTOT * KD];    // sampled A fp16, [m][2304]
__device__ __align__(16) __half g_xTp[BB * PP * CI];       // fp16 x, padded transposed (hw, c)
__device__ __align__(16) ushort4 g_tidx[9 * MTOT];         // corner PADDED row indices
__device__ __align__(16) uint4   g_tw2[9 * MTOT];          // corner weights as 4x half2
__device__ __align__(16) __half g_rawh[BB * CO * HW];      // pre-BN output (fp16)
__device__ float g_sum[CO];
__device__ float g_sum2[CO];

// ---------------- helpers ----------------
__device__ __forceinline__ uint32_t smem_u32(const void* p) {
    uint32_t a;
    asm("{ .reg .u64 t; cvta.to.shared.u64 t, %1; cvt.u32.u64 %0, t; }" : "=r"(a) : "l"(p));
    return a;
}
__device__ __forceinline__ uint32_t pack_h2(float lo, float hi) {
    __half2 h = __floats2half2_rn(lo, hi);
    return *(uint32_t*)&h;
}
__device__ __forceinline__ void mma_f16(float* d, const uint32_t* a,
                                        uint32_t b0, uint32_t b1) {
    asm volatile(
        "mma.sync.aligned.m16n8k16.row.col.f32.f16.f16.f32 "
        "{%0,%1,%2,%3}, {%4,%5,%6,%7}, {%8,%9}, {%0,%1,%2,%3};"
        : "+f"(d[0]), "+f"(d[1]), "+f"(d[2]), "+f"(d[3])
        : "r"(a[0]), "r"(a[1]), "r"(a[2]), "r"(a[3]), "r"(b0), "r"(b1));
}
__device__ __forceinline__ void cp_async16(uint32_t saddr, const void* gaddr) {
    asm volatile("cp.async.cg.shared.global [%0], [%1], 16;" :: "r"(saddr), "l"(gaddr));
}
__device__ __forceinline__ uint32_t h2dot(uint32_t c0, uint32_t c1, uint32_t c2, uint32_t c3,
                                          __half2 w0, __half2 w1, __half2 w2, __half2 w3) {
    __half2 r = __hmul2(w0, *(__half2*)&c0);
    r = __hfma2(w1, *(__half2*)&c1, r);
    r = __hfma2(w2, *(__half2*)&c2, r);
    r = __hfma2(w3, *(__half2*)&c3, r);
    return *(uint32_t*)&r;
}

// bilinear table construction for one (pixel, tap)
__device__ __forceinline__ void make_tab(int b, int hw, int k, float offy, float offx) {
    int h = hw >> 6, w = hw & 63;
    int k3 = k / 3;
    float py = (float)(h + k3 - 1) + offy;
    float px = (float)(w + (k - k3 * 3) - 1) + offx;
    float fy0 = floorf(py), fx0 = floorf(px);
    float wy1 = py - fy0, wx1 = px - fx0;
    float wy0 = 1.f - wy1, wx0 = 1.f - wx1;
    int iy0 = (int)fy0, ix0 = (int)fx0;
    int iy1 = iy0 + 1, ix1 = ix0 + 1;
    float vy0 = (iy0 >= 0 && iy0 < HH) ? 1.f : 0.f;
    float vy1 = (iy1 >= 0 && iy1 < HH) ? 1.f : 0.f;
    float vx0 = (ix0 >= 0 && ix0 < WW) ? 1.f : 0.f;
    float vx1 = (ix1 >= 0 && ix1 < WW) ? 1.f : 0.f;
    int cy0 = min(max(iy0, 0), HH - 1), cy1 = min(max(iy1, 0), HH - 1);
    int cx0 = min(max(ix0, 0), WW - 1), cx1 = min(max(ix1, 0), WW - 1);
    ushort4 gi;
    gi.x = (unsigned short)((cy0 + 1) * 66 + cx0 + 1);
    gi.y = (unsigned short)((cy0 + 1) * 66 + cx1 + 1);
    gi.z = (unsigned short)((cy1 + 1) * 66 + cx0 + 1);
    gi.w = (unsigned short)((cy1 + 1) * 66 + cx1 + 1);
    int idx = (k << 14) + (b << 12) + hw;
    g_tidx[idx] = gi;
    float w00 = wy0 * wx0 * vy0 * vx0;
    float w01 = wy0 * wx1 * vy0 * vx1;
    float w10 = wy1 * wx0 * vy1 * vx0;
    float w11 = wy1 * wx1 * vy1 * vx1;
    uint4 wq;
    wq.x = pack_h2(w00, w00);
    wq.y = pack_h2(w01, w01);
    wq.z = pack_h2(w10, w10);
    wq.w = pack_h2(w11, w11);
    g_tw2[idx] = wq;
}

// ---------------- kernel: unified prep (xhT + wB + pad + wOffB + stats) ----
#define N_WB   (NCHUNK * 4096)
#define N_PAD  (BB * 260 * 32)
#define N_WOFF (NCHUNK * 384)
#define N_MISC (N_WB + N_PAD + N_WOFF + 256)    // 356096 = 1391*256
#define NB_XHT (BB * HH * 4)                    // 1024 transpose blocks
#define NB_PREP (NB_XHT + N_MISC / 256)         // 2415

__global__ void prep_all(const float* __restrict__ x,
                         const float* __restrict__ w_conv,
                         const float* __restrict__ w_off) {
    __shared__ float tile[64][65];
    int blk = blockIdx.x;
    int t = threadIdx.x;
    if (blk < NB_XHT) {
        int bh = blk & 255;
        int c0 = (blk >> 8) * 64;
        int b = bh >> 6, h = bh & 63;
        int ci = t >> 6, w = t & 63;
#pragma unroll
        for (int rep = 0; rep < 16; rep++) {
            int c = c0 + ci + rep * 4;
            tile[ci + rep * 4][w] = x[((size_t)(b * CI + c) << 12) + h * 64 + w];
        }
        __syncthreads();
#pragma unroll
        for (int rep = 0; rep < 2; rep++) {
            int e = t + rep * 256;
            int w2 = e & 63, q = e >> 6;
            __half hv[8];
#pragma unroll
            for (int j = 0; j < 8; j++) hv[j] = __float2half(tile[q * 8 + j][w2]);
            size_t dst = ((size_t)b * PP + (h + 1) * 66 + (w2 + 1)) * CI + c0 + q * 8;
            *(uint4*)(g_xTp + dst) = *(uint4*)hv;
        }
        return;
    }
    int idx = (blk - NB_XHT) * 256 + t;
    if (idx < N_WB) {
        int kt = idx >> 12;
        int r  = idx & 4095;
        int k16  = r >> 11;
        int np   = (r >> 7) & 15;
        int lane = (r >> 2) & 31;
        int w    = r & 3;
        int g = lane >> 2, tg = lane & 3;
        int nt = np * 2 + (w >> 1);
        int h  = w & 1;
        int n  = nt * 8 + g;
        int ck = kt * 32 + k16 * 16 + h * 8 + 2 * tg;   // tap-major k index
        int tap = ck >> 8;
        int c   = ck & 255;
        g_wB[idx] = pack_h2(w_conv[n * KD + c * 9 + tap],
                            w_conv[n * KD + (c + 1) * 9 + tap]);
        return;
    }
    idx -= N_WB;
    if (idx < N_PAD) {
        int q = idx & 31;
        int r = (idx >> 5) % 260;
        int b = idx / (260 * 32);
        int row;
        if (r < 66)       row = r;
        else if (r < 132) row = 65 * 66 + (r - 66);
        else if (r < 196) row = (r - 132 + 1) * 66;
        else              row = (r - 196 + 1) * 66 + 65;
        ((uint4*)(g_xTp + ((size_t)b * PP + row) * CI))[q] = make_uint4(0, 0, 0, 0);
        return;
    }
    idx -= N_PAD;
    if (idx < N_WOFF) {
        int kt = idx / 384;
        int r  = idx - kt * 384;
        int k16  = r / 192;
        int nt   = (r / 64) % 3;
        int lane = (r >> 1) & 31;
        int h    = r & 1;
        int g = lane >> 2, tg = lane & 3;
        int n = nt * 8 + g;
        int tap = kt >> 3;
        int c = (kt & 7) * 32 + k16 * 16 + h * 8 + 2 * tg;
        uint32_t val = 0;
        if (n < 18)
            val = pack_h2(w_off[n * KD + c * 9 + tap], w_off[n * KD + (c + 1) * 9 + tap]);
        g_wOffB[idx] = val;
        return;
    }
    idx -= N_WOFF;
    if (idx < 256) {
        g_sum[idx] = 0.f;
        g_sum2[idx] = 0.f;
    }
}

// ---------------- kernel: offset conv GEMM + fused bilinear tables ---------
__global__ void __launch_bounds__(128)
offset_gemm(const float* __restrict__ b_off) {
    __shared__ __align__(16) char As[3 * 4096];
    __shared__ __align__(16) char Bs[3 * 1536];
    const uint32_t Ab0 = smem_u32(As);
    const uint32_t Bb0 = smem_u32(Bs);
    const int t = threadIdx.x;
    const int lane = t & 31;
    const int wm = t >> 5;
    const int g = lane >> 2;
    const int tg = lane & 3;
    const int m0 = blockIdx.x << 6;
    const int b  = m0 >> 12;

    const int ar = t & 63;
    const int part = t >> 6;
    const int hw_a = (m0 + ar) & 4095;
    const int prow = ((hw_a >> 6) + 1) * 66 + (hw_a & 63) + 1;
    const __half* arow = g_xTp + ((size_t)b * PP + prow) * CI;
    const int rp = ar >> 1;
    const uint32_t dstA_base = rp * 128;

    auto issue = [&](int kt, int s) {
        int tap = kt >> 3;
        int shift = (tap / 3 - 1) * 66 + (tap % 3 - 1);
        const __half* src = arow + (size_t)shift * CI + (kt & 7) * 32;
#pragma unroll
        for (int qq = 0; qq < 2; qq++) {
            int q = part * 2 + qq;
            uint32_t cc = ((ar & 1) << 2) + q;
            cp_async16(Ab0 + s * 4096 + dstA_base + ((cc ^ (rp & 7)) << 4), src + q * 8);
        }
        if (t < 96)
            cp_async16(Bb0 + s * 1536 + t * 16, g_wOffB + kt * 384 + t * 4);
        asm volatile("cp.async.commit_group;" ::: "memory");
    };

    float acc[3][4];
#pragma unroll
    for (int nt = 0; nt < 3; nt++)
#pragma unroll
        for (int r = 0; r < 4; r++) acc[nt][r] = 0.f;

    auto compute = [&](int s) {
        const uint32_t Ab = Ab0 + s * 4096;
        const uint32_t Bb = Bb0 + s * 1536;
#pragma unroll
        for (int k16 = 0; k16 < 2; k16++) {
            uint32_t a[4];
            {
                int mr = wm * 16;
                int tt = lane >> 3, r = lane & 7;
                int mrow = mr + ((tt & 1) << 3) + r;
                int rp2 = mrow >> 1;
                int cc = ((mrow & 1) << 2) + (k16 << 1) + (tt >> 1);
                uint32_t addr = Ab + rp2 * 128 + ((cc ^ (rp2 & 7)) << 4);
                asm volatile(
                    "ldmatrix.sync.aligned.m8n8.x4.shared.b16 {%0,%1,%2,%3}, [%4];"
                    : "=r"(a[0]), "=r"(a[1]), "=r"(a[2]), "=r"(a[3])
                    : "r"(addr));
            }
#pragma unroll
            for (int nt = 0; nt < 3; nt++) {
                uint32_t b0, b1;
                uint32_t addr = Bb + ((k16 * 3 + nt) * 64 + lane * 2) * 4;
                asm volatile("ld.shared.v2.u32 {%0,%1}, [%2];"
                             : "=r"(b0), "=r"(b1) : "r"(addr));
                mma_f16(acc[nt], a, b0, b1);
            }
        }
    };

    issue(0, 0);
    issue(1, 1);
    asm volatile("cp.async.wait_group 1;" ::: "memory");
    __syncthreads();

#pragma unroll 1
    for (int it = 0; it < NCHUNK / 3; it++) {
        int kt = it * 3;
        compute(0);
        if (kt + 2 < NCHUNK) {
            issue(kt + 2, 2);
            asm volatile("cp.async.wait_group 1;" ::: "memory");
        } else {
            asm volatile("cp.async.wait_group 0;" ::: "memory");
        }
        __syncthreads();
        compute(1);
        if (kt + 3 < NCHUNK) {
            issue(kt + 3, 0);
            asm volatile("cp.async.wait_group 1;" ::: "memory");
        } else {
            asm volatile("cp.async.wait_group 0;" ::: "memory");
        }
        __syncthreads();
        compute(2);
        if (kt + 4 < NCHUNK) {
            issue(kt + 4, 1);
            asm volatile("cp.async.wait_group 1;" ::: "memory");
        } else {
            asm volatile("cp.async.wait_group 0;" ::: "memory");
        }
        __syncthreads();
    }

#pragma unroll
    for (int nt = 0; nt < 3; nt++) {
        int k = nt * 4 + tg;
        if (k < 9) {
            float by0 = b_off[2 * k];
            float by1 = b_off[2 * k + 1];
            int hw0 = (m0 & 4095) + wm * 16 + g;
            make_tab(b, hw0,     k, acc[nt][0] + by0, acc[nt][1] + by1);
            make_tab(b, hw0 + 8, k, acc[nt][2] + by0, acc[nt][3] + by1);
        }
    }
}

// ---------------- kernel: pipelined channel-vector gather (1 pixel/warp) ---
__global__ void __launch_bounds__(256) gather_A_kernel() {
    const int lane = threadIdx.x & 31;
    const int wid  = threadIdx.x >> 5;
    const int m = (blockIdx.x << 3) + wid;
    const int b = m >> 12;
    const __half* basep = g_xTp + (size_t)b * PP * CI;
    __half* dstm = g_A + (size_t)m * KD + lane * 8;

    ushort4 gi = g_tidx[m];
    uint4 wq   = g_tw2[m];
    uint4 a0 = __ldg((const uint4*)(basep + (int)gi.x * CI) + lane);
    uint4 a1 = __ldg((const uint4*)(basep + (int)gi.y * CI) + lane);
    uint4 a2 = __ldg((const uint4*)(basep + (int)gi.z * CI) + lane);
    uint4 a3 = __ldg((const uint4*)(basep + (int)gi.w * CI) + lane);

#pragma unroll
    for (int tap = 0; tap < 9; tap++) {
        uint4 n0, n1, n2, n3, wqn;
        if (tap < 8) {
            int idx = ((tap + 1) << 14) + m;
            ushort4 gin = g_tidx[idx];
            wqn = g_tw2[idx];
            n0 = __ldg((const uint4*)(basep + (int)gin.x * CI) + lane);
            n1 = __ldg((const uint4*)(basep + (int)gin.y * CI) + lane);
            n2 = __ldg((const uint4*)(basep + (int)gin.z * CI) + lane);
            n3 = __ldg((const uint4*)(basep + (int)gin.w * CI) + lane);
        }
        __half2 w0 = *(__half2*)&wq.x, w1 = *(__half2*)&wq.y;
        __half2 w2 = *(__half2*)&wq.z, w3 = *(__half2*)&wq.w;
        uint4 o;
        o.x = h2dot(a0.x, a1.x, a2.x, a3.x, w0, w1, w2, w3);
        o.y = h2dot(a0.y, a1.y, a2.y, a3.y, w0, w1, w2, w3);
        o.z = h2dot(a0.z, a1.z, a2.z, a3.z, w0, w1, w2, w3);
        o.w = h2dot(a0.w, a1.w, a2.w, a3.w, w0, w1, w2, w3);
        *(uint4*)(dstm + tap * 256) = o;
        if (tap < 8) {
            a0 = n0; a1 = n1; a2 = n2; a3 = n3; wq = wqn;
        }
    }
}

// ---------------- kernel: pipelined fp16 HMMA GEMM (512 thr, 4x4 warps) ----
#define ST_A 16384
#define ST_B 16384
#define OFF_A 0
#define OFF_B (3 * ST_A)
#define SMEM_GEMM (3 * ST_A + 3 * ST_B)     // 98304

__global__ void __launch_bounds__(512, 2)
gemm_main() {
    extern __shared__ char smem[];
    const uint32_t sb = smem_u32(smem);
    const int tid  = threadIdx.x;
    const int lane = tid & 31;
    const int wid  = tid >> 5;
    const int g  = lane >> 2;
    const int tg = lane & 3;
    const int wm = wid & 3;
    const int wn = wid >> 2;                // 0..3
    const int m0 = blockIdx.x << 7;
    const int by = blockIdx.y;
    const int b  = m0 >> 12;

    // cp.async A mapping: 512 threads cover 128 m x 4 uint4 (one 64k chunk = 512 cp16)
    const int cm  = tid & 127;
    const int ckl = tid >> 7;               // 0..3

    auto issue = [&](int kt, int s) {
        const __half* arow = g_A + (size_t)(m0 + cm) * KD + kt * 64;
#pragma unroll
        for (int sub = 0; sub < 2; sub++) {
            uint32_t dstA = (uint32_t)(sub * 8192 + (cm >> 1) * 128
                         + (((((cm & 1) << 2) + ckl) ^ ((cm >> 1) & 7)) << 4));
            cp_async16(sb + OFF_A + s * ST_A + dstA, arow + sub * 32 + ckl * 8);
        }
        const float4* wb4 = (const float4*)g_wB;
#pragma unroll
        for (int r = 0; r < 2; r++) {
            int idx = r * 512 + tid;
            int sub = idx >> 9;
            int i2  = idx & 511;
            int k16 = i2 >> 8;
            int npl = (i2 >> 5) & 7;
            int ln  = i2 & 31;
            cp_async16(sb + OFF_B + s * ST_B + idx * 16,
                       wb4 + (size_t)(2 * kt + sub) * 1024 + k16 * 512
                           + (8 * by + npl) * 32 + ln);
        }
        asm volatile("cp.async.commit_group;" ::: "memory");
    };

    // warp tile 32m x 32n: 2 mt x 4 nt of m16n8
    float acc[2][4][4];
#pragma unroll
    for (int mt = 0; mt < 2; mt++)
#pragma unroll
        for (int nt = 0; nt < 4; nt++)
#pragma unroll
            for (int r = 0; r < 4; r++) acc[mt][nt][r] = 0.f;

    auto compute = [&](int s) {
#pragma unroll
        for (int k32 = 0; k32 < 2; k32++) {
            const uint32_t Ab = sb + OFF_A + s * ST_A + k32 * 8192;
            const uint32_t Bb = sb + OFF_B + s * ST_B + k32 * 8192;
#pragma unroll
            for (int k16 = 0; k16 < 2; k16++) {
                uint32_t a[2][4];
#pragma unroll
                for (int mt = 0; mt < 2; mt++) {
                    int mr = wm * 32 + mt * 16;
                    int t = lane >> 3, r = lane & 7;
                    int mrow = mr + ((t & 1) << 3) + r;
                    int rp = mrow >> 1;
                    int cc = ((mrow & 1) << 2) + (k16 << 1) + (t >> 1);
                    uint32_t addr = Ab + rp * 128 + ((cc ^ (rp & 7)) << 4);
                    asm volatile(
                        "ldmatrix.sync.aligned.m8n8.x4.shared.b16 {%0,%1,%2,%3}, [%4];"
                        : "=r"(a[mt][0]), "=r"(a[mt][1]), "=r"(a[mt][2]), "=r"(a[mt][3])
                        : "r"(addr));
                }
#pragma unroll
                for (int j = 0; j < 2; j++) {
                    uint32_t b0, b1, b2, b3;
                    uint32_t addr = Bb + (((k16 * 8) + wn * 2 + j) * 32 + lane) * 16;
                    asm volatile("ld.shared.v4.u32 {%0,%1,%2,%3}, [%4];"
                                 : "=r"(b0), "=r"(b1), "=r"(b2), "=r"(b3) : "r"(addr));
                    mma_f16(acc[0][2 * j],     a[0], b0, b1);
                    mma_f16(acc[1][2 * j],     a[1], b0, b1);
                    mma_f16(acc[0][2 * j + 1], a[0], b2, b3);
                    mma_f16(acc[1][2 * j + 1], a[1], b2, b3);
                }
            }
        }
    };

    issue(0, 0);
    issue(1, 1);
    asm volatile("cp.async.wait_group 1;" ::: "memory");
    __syncthreads();

#pragma unroll 1
    for (int it = 0; it < NKT2 / 3; it++) {
        int kt = it * 3;
        compute(0);
        if (kt + 2 < NKT2) {
            issue(kt + 2, 2);
            asm volatile("cp.async.wait_group 1;" ::: "memory");
        } else {
            asm volatile("cp.async.wait_group 0;" ::: "memory");
        }
        __syncthreads();
        compute(1);
        if (kt + 3 < NKT2) {
            issue(kt + 3, 0);
            asm volatile("cp.async.wait_group 1;" ::: "memory");
        } else {
            asm volatile("cp.async.wait_group 0;" ::: "memory");
        }
        __syncthreads();
        compute(2);
        if (kt + 4 < NKT2) {
            issue(kt + 4, 1);
            asm volatile("cp.async.wait_group 1;" ::: "memory");
        } else {
            asm volatile("cp.async.wait_group 0;" ::: "memory");
        }
        __syncthreads();
    }

    // epilogue: warp covers n = by*128 + wn*32 + nt*8 + 2tg, m rows wm*32..
    const int hwb = (m0 & 4095);
#pragma unroll
    for (int nt = 0; nt < 4; nt++) {
        int n = by * 128 + wn * 32 + nt * 8 + 2 * tg;
        __half* p0 = g_rawh + ((size_t)(b * CO + n) << 12);
        __half* p1 = p0 + HW;
        float s0 = 0.f, q0 = 0.f, s1 = 0.f, q1 = 0.f;
#pragma unroll
        for (int mt = 0; mt < 2; mt++) {
            int hw0 = hwb + wm * 32 + mt * 16 + g;
            float d0 = acc[mt][nt][0], d1 = acc[mt][nt][1];
            float d2 = acc[mt][nt][2], d3 = acc[mt][nt][3];
            p0[hw0]     = __float2half(d0);
            p1[hw0]     = __float2half(d1);
            p0[hw0 + 8] = __float2half(d2);
            p1[hw0 + 8] = __float2half(d3);
            s0 += d0 + d2;  q0 += d0 * d0 + d2 * d2;
            s1 += d1 + d3;  q1 += d1 * d1 + d3 * d3;
        }
#pragma unroll
        for (int o = 4; o < 32; o <<= 1) {
            s0 += __shfl_xor_sync(0xFFFFFFFF, s0, o);
            q0 += __shfl_xor_sync(0xFFFFFFFF, q0, o);
            s1 += __shfl_xor_sync(0xFFFFFFFF, s1, o);
            q1 += __shfl_xor_sync(0xFFFFFFFF, q1, o);
        }
        if (lane < 4) {
            atomicAdd(&g_sum[n], s0);
            atomicAdd(&g_sum2[n], q0);
            atomicAdd(&g_sum[n + 1], s1);
            atomicAdd(&g_sum2[n + 1], q1);
        }
    }
}

// ---------------- BN finalize + apply (fused, fp16 raw) ---------------------
__global__ void bn_apply(float* __restrict__ out,
                         const float* __restrict__ gamma,
                         const float* __restrict__ beta) {
    __shared__ float ssc[256], ssh[256];
    int t = threadIdx.x;
    {
        float mean = g_sum[t] * (1.f / 16384.f);
        float var  = g_sum2[t] * (1.f / 16384.f) - mean * mean;
        float inv  = gamma[t] * rsqrtf(var + 1e-5f);
        ssc[t] = inv;
        ssh[t] = beta[t] - mean * inv;
    }
    __syncthreads();
    int i = blockIdx.x * 256 + t;           // uint4-of-half index (8 elems)
    int o = (i >> 9) & 255;
    uint4 v = ((const uint4*)g_rawh)[i];
    float sc = ssc[o], sf = ssh[o];
    float2 f0 = __half22float2(*(__half2*)&v.x);
    float2 f1 = __half22float2(*(__half2*)&v.y);
    float2 f2 = __half22float2(*(__half2*)&v.z);
    float2 f3 = __half22float2(*(__half2*)&v.w);
    float4 q0, q1;
    q0.x = fmaxf(f0.x * sc + sf, 0.f);
    q0.y = fmaxf(f0.y * sc + sf, 0.f);
    q0.z = fmaxf(f1.x * sc + sf, 0.f);
    q0.w = fmaxf(f1.y * sc + sf, 0.f);
    q1.x = fmaxf(f2.x * sc + sf, 0.f);
    q1.y = fmaxf(f2.y * sc + sf, 0.f);
    q1.z = fmaxf(f3.x * sc + sf, 0.f);
    q1.w = fmaxf(f3.y * sc + sf, 0.f);
    ((float4*)out)[2 * i]     = q0;
    ((float4*)out)[2 * i + 1] = q1;
}

// ---------------- launch ----------------
extern "C" void kernel_launch(void* const* d_in, const int* in_sizes, int n_in,
                              void* d_out, int out_size) {
    const float* x      = (const float*)d_in[0];
    const float* w_off  = (const float*)d_in[1];
    const float* b_off  = (const float*)d_in[2];
    const float* w_conv = (const float*)d_in[3];
    const float* gamma  = (const float*)d_in[4];
    const float* beta   = (const float*)d_in[5];
    float* out = (float*)d_out;

    cudaFuncSetAttribute(gemm_main,
                         cudaFuncAttributeMaxDynamicSharedMemorySize, SMEM_GEMM);

    prep_all<<<NB_PREP, 256>>>(x, w_conv, w_off);
    offset_gemm<<<MTOT / 64, 128>>>(b_off);
    gather_A_kernel<<<MTOT / 8, 256>>>();
    gemm_main<<<dim3(MTOT / 128, 2), 512, SMEM_GEMM>>>();
    bn_apply<<<(BB * CO * HW / 8) / 256, 256>>>(out, gamma, beta);
}

// round 16
// speedup vs baseline: 1.0282x; 1.0282x over previous
#include <cuda_runtime.h>
#include <cuda_fp16.h>
#include <cstdint>

#define BB 4
#define CI 256
#define CO 256
#define HH 64
#define WW 64
#define HW 4096
#define KD 2304          // CI * 9
#define MTOT 16384
#define NCHUNK 72        // KD / 32  (B packing granularity)
#define NKT2 36          // KD / 64  (gemm main-loop chunks)
#define PP 4356          // 66*66 padded pixels

// ---------------- scratch ----------------
__device__ __align__(16) uint32_t g_wB[NCHUNK * 4096];     // frag-ordered fp16 B (main, tap-major k)
__device__ __align__(16) uint32_t g_wOffB[NCHUNK * 384];   // frag-ordered fp16 B (offset)
__device__ __align__(16) __half g_A[(size_t)MTOT * KD];    // sampled A fp16, [m][2304]
__device__ __align__(16) __half g_xTp[BB * PP * CI];       // fp16 x, padded transposed (hw, c)
__device__ __align__(16) ushort4 g_tidx[9 * MTOT];         // corner PADDED row indices
__device__ __align__(16) uint4   g_tw2[9 * MTOT];          // corner weights as 4x half2
__device__ __align__(16) __half g_rawh[BB * CO * HW];      // pre-BN output (fp16)
__device__ float g_sum[CO];
__device__ float g_sum2[CO];

// ---------------- helpers ----------------
__device__ __forceinline__ uint32_t smem_u32(const void* p) {
    uint32_t a;
    asm("{ .reg .u64 t; cvta.to.shared.u64 t, %1; cvt.u32.u64 %0, t; }" : "=r"(a) : "l"(p));
    return a;
}
__device__ __forceinline__ uint32_t pack_h2(float lo, float hi) {
    __half2 h = __floats2half2_rn(lo, hi);
    return *(uint32_t*)&h;
}
__device__ __forceinline__ void mma_f16(float* d, const uint32_t* a,
                                        uint32_t b0, uint32_t b1) {
    asm volatile(
        "mma.sync.aligned.m16n8k16.row.col.f32.f16.f16.f32 "
        "{%0,%1,%2,%3}, {%4,%5,%6,%7}, {%8,%9}, {%0,%1,%2,%3};"
        : "+f"(d[0]), "+f"(d[1]), "+f"(d[2]), "+f"(d[3])
        : "r"(a[0]), "r"(a[1]), "r"(a[2]), "r"(a[3]), "r"(b0), "r"(b1));
}
__device__ __forceinline__ void cp_async16(uint32_t saddr, const void* gaddr) {
    asm volatile("cp.async.cg.shared.global [%0], [%1], 16;" :: "r"(saddr), "l"(gaddr));
}
__device__ __forceinline__ uint32_t h2dot(uint32_t c0, uint32_t c1, uint32_t c2, uint32_t c3,
                                          __half2 w0, __half2 w1, __half2 w2, __half2 w3) {
    __half2 r = __hmul2(w0, *(__half2*)&c0);
    r = __hfma2(w1, *(__half2*)&c1, r);
    r = __hfma2(w2, *(__half2*)&c2, r);
    r = __hfma2(w3, *(__half2*)&c3, r);
    return *(uint32_t*)&r;
}

// bilinear table construction for one (pixel, tap)
__device__ __forceinline__ void make_tab(int b, int hw, int k, float offy, float offx) {
    int h = hw >> 6, w = hw & 63;
    int k3 = k / 3;
    float py = (float)(h + k3 - 1) + offy;
    float px = (float)(w + (k - k3 * 3) - 1) + offx;
    float fy0 = floorf(py), fx0 = floorf(px);
    float wy1 = py - fy0, wx1 = px - fx0;
    float wy0 = 1.f - wy1, wx0 = 1.f - wx1;
    int iy0 = (int)fy0, ix0 = (int)fx0;
    int iy1 = iy0 + 1, ix1 = ix0 + 1;
    float vy0 = (iy0 >= 0 && iy0 < HH) ? 1.f : 0.f;
    float vy1 = (iy1 >= 0 && iy1 < HH) ? 1.f : 0.f;
    float vx0 = (ix0 >= 0 && ix0 < WW) ? 1.f : 0.f;
    float vx1 = (ix1 >= 0 && ix1 < WW) ? 1.f : 0.f;
    int cy0 = min(max(iy0, 0), HH - 1), cy1 = min(max(iy1, 0), HH - 1);
    int cx0 = min(max(ix0, 0), WW - 1), cx1 = min(max(ix1, 0), WW - 1);
    ushort4 gi;
    gi.x = (unsigned short)((cy0 + 1) * 66 + cx0 + 1);
    gi.y = (unsigned short)((cy0 + 1) * 66 + cx1 + 1);
    gi.z = (unsigned short)((cy1 + 1) * 66 + cx0 + 1);
    gi.w = (unsigned short)((cy1 + 1) * 66 + cx1 + 1);
    int idx = (k << 14) + (b << 12) + hw;
    g_tidx[idx] = gi;
    float w00 = wy0 * wx0 * vy0 * vx0;
    float w01 = wy0 * wx1 * vy0 * vx1;
    float w10 = wy1 * wx0 * vy1 * vx0;
    float w11 = wy1 * wx1 * vy1 * vx1;
    uint4 wq;
    wq.x = pack_h2(w00, w00);
    wq.y = pack_h2(w01, w01);
    wq.z = pack_h2(w10, w10);
    wq.w = pack_h2(w11, w11);
    g_tw2[idx] = wq;
}

// ---------------- kernel: unified prep (xhT + wB + pad + wOffB + stats) ----
#define N_WB   (NCHUNK * 4096)
#define N_PAD  (BB * 260 * 32)
#define N_WOFF (NCHUNK * 384)
#define N_MISC (N_WB + N_PAD + N_WOFF + 256)    // 356096 = 1391*256
#define NB_XHT (BB * HH * 4)                    // 1024 transpose blocks
#define NB_PREP (NB_XHT + N_MISC / 256)         // 2415

__global__ void prep_all(const float* __restrict__ x,
                         const float* __restrict__ w_conv,
                         const float* __restrict__ w_off) {
    __shared__ float tile[64][65];
    int blk = blockIdx.x;
    int t = threadIdx.x;
    if (blk < NB_XHT) {
        int bh = blk & 255;
        int c0 = (blk >> 8) * 64;
        int b = bh >> 6, h = bh & 63;
        int ci = t >> 6, w = t & 63;
#pragma unroll
        for (int rep = 0; rep < 16; rep++) {
            int c = c0 + ci + rep * 4;
            tile[ci + rep * 4][w] = x[((size_t)(b * CI + c) << 12) + h * 64 + w];
        }
        __syncthreads();
#pragma unroll
        for (int rep = 0; rep < 2; rep++) {
            int e = t + rep * 256;
            int w2 = e & 63, q = e >> 6;
            __half hv[8];
#pragma unroll
            for (int j = 0; j < 8; j++) hv[j] = __float2half(tile[q * 8 + j][w2]);
            size_t dst = ((size_t)b * PP + (h + 1) * 66 + (w2 + 1)) * CI + c0 + q * 8;
            *(uint4*)(g_xTp + dst) = *(uint4*)hv;
        }
        return;
    }
    int idx = (blk - NB_XHT) * 256 + t;
    if (idx < N_WB) {
        int kt = idx >> 12;
        int r  = idx & 4095;
        int k16  = r >> 11;
        int np   = (r >> 7) & 15;
        int lane = (r >> 2) & 31;
        int w    = r & 3;
        int g = lane >> 2, tg = lane & 3;
        int nt = np * 2 + (w >> 1);
        int h  = w & 1;
        int n  = nt * 8 + g;
        int ck = kt * 32 + k16 * 16 + h * 8 + 2 * tg;   // tap-major k index
        int tap = ck >> 8;
        int c   = ck & 255;
        g_wB[idx] = pack_h2(w_conv[n * KD + c * 9 + tap],
                            w_conv[n * KD + (c + 1) * 9 + tap]);
        return;
    }
    idx -= N_WB;
    if (idx < N_PAD) {
        int q = idx & 31;
        int r = (idx >> 5) % 260;
        int b = idx / (260 * 32);
        int row;
        if (r < 66)       row = r;
        else if (r < 132) row = 65 * 66 + (r - 66);
        else if (r < 196) row = (r - 132 + 1) * 66;
        else              row = (r - 196 + 1) * 66 + 65;
        ((uint4*)(g_xTp + ((size_t)b * PP + row) * CI))[q] = make_uint4(0, 0, 0, 0);
        return;
    }
    idx -= N_PAD;
    if (idx < N_WOFF) {
        int kt = idx / 384;
        int r  = idx - kt * 384;
        int k16  = r / 192;
        int nt   = (r / 64) % 3;
        int lane = (r >> 1) & 31;
        int h    = r & 1;
        int g = lane >> 2, tg = lane & 3;
        int n = nt * 8 + g;
        int tap = kt >> 3;
        int c = (kt & 7) * 32 + k16 * 16 + h * 8 + 2 * tg;
        uint32_t val = 0;
        if (n < 18)
            val = pack_h2(w_off[n * KD + c * 9 + tap], w_off[n * KD + (c + 1) * 9 + tap]);
        g_wOffB[idx] = val;
        return;
    }
    idx -= N_WOFF;
    if (idx < 256) {
        g_sum[idx] = 0.f;
        g_sum2[idx] = 0.f;
    }
}

// ---------------- kernel: offset conv GEMM + fused bilinear tables ---------
__global__ void __launch_bounds__(128)
offset_gemm(const float* __restrict__ b_off) {
    __shared__ __align__(16) char As[3 * 4096];
    __shared__ __align__(16) char Bs[3 * 1536];
    const uint32_t Ab0 = smem_u32(As);
    const uint32_t Bb0 = smem_u32(Bs);
    const int t = threadIdx.x;
    const int lane = t & 31;
    const int wm = t >> 5;
    const int g = lane >> 2;
    const int tg = lane & 3;
    const int m0 = blockIdx.x << 6;
    const int b  = m0 >> 12;

    const int ar = t & 63;
    const int part = t >> 6;
    const int hw_a = (m0 + ar) & 4095;
    const int prow = ((hw_a >> 6) + 1) * 66 + (hw_a & 63) + 1;
    const __half* arow = g_xTp + ((size_t)b * PP + prow) * CI;
    const int rp = ar >> 1;
    const uint32_t dstA_base = rp * 128;

    auto issue = [&](int kt, int s) {
        int tap = kt >> 3;
        int shift = (tap / 3 - 1) * 66 + (tap % 3 - 1);
        const __half* src = arow + (size_t)shift * CI + (kt & 7) * 32;
#pragma unroll
        for (int qq = 0; qq < 2; qq++) {
            int q = part * 2 + qq;
            uint32_t cc = ((ar & 1) << 2) + q;
            cp_async16(Ab0 + s * 4096 + dstA_base + ((cc ^ (rp & 7)) << 4), src + q * 8);
        }
        if (t < 96)
            cp_async16(Bb0 + s * 1536 + t * 16, g_wOffB + kt * 384 + t * 4);
        asm volatile("cp.async.commit_group;" ::: "memory");
    };

    float acc[3][4];
#pragma unroll
    for (int nt = 0; nt < 3; nt++)
#pragma unroll
        for (int r = 0; r < 4; r++) acc[nt][r] = 0.f;

    auto compute = [&](int s) {
        const uint32_t Ab = Ab0 + s * 4096;
        const uint32_t Bb = Bb0 + s * 1536;
#pragma unroll
        for (int k16 = 0; k16 < 2; k16++) {
            uint32_t a[4];
            {
                int mr = wm * 16;
                int tt = lane >> 3, r = lane & 7;
                int mrow = mr + ((tt & 1) << 3) + r;
                int rp2 = mrow >> 1;
                int cc = ((mrow & 1) << 2) + (k16 << 1) + (tt >> 1);
                uint32_t addr = Ab + rp2 * 128 + ((cc ^ (rp2 & 7)) << 4);
                asm volatile(
                    "ldmatrix.sync.aligned.m8n8.x4.shared.b16 {%0,%1,%2,%3}, [%4];"
                    : "=r"(a[0]), "=r"(a[1]), "=r"(a[2]), "=r"(a[3])
                    : "r"(addr));
            }
#pragma unroll
            for (int nt = 0; nt < 3; nt++) {
                uint32_t b0, b1;
                uint32_t addr = Bb + ((k16 * 3 + nt) * 64 + lane * 2) * 4;
                asm volatile("ld.shared.v2.u32 {%0,%1}, [%2];"
                             : "=r"(b0), "=r"(b1) : "r"(addr));
                mma_f16(acc[nt], a, b0, b1);
            }
        }
    };

    issue(0, 0);
    issue(1, 1);
    asm volatile("cp.async.wait_group 1;" ::: "memory");
    __syncthreads();

#pragma unroll 1
    for (int it = 0; it < NCHUNK / 3; it++) {
        int kt = it * 3;
        compute(0);
        if (kt + 2 < NCHUNK) {
            issue(kt + 2, 2);
            asm volatile("cp.async.wait_group 1;" ::: "memory");
        } else {
            asm volatile("cp.async.wait_group 0;" ::: "memory");
        }
        __syncthreads();
        compute(1);
        if (kt + 3 < NCHUNK) {
            issue(kt + 3, 0);
            asm volatile("cp.async.wait_group 1;" ::: "memory");
        } else {
            asm volatile("cp.async.wait_group 0;" ::: "memory");
        }
        __syncthreads();
        compute(2);
        if (kt + 4 < NCHUNK) {
            issue(kt + 4, 1);
            asm volatile("cp.async.wait_group 1;" ::: "memory");
        } else {
            asm volatile("cp.async.wait_group 0;" ::: "memory");
        }
        __syncthreads();
    }

#pragma unroll
    for (int nt = 0; nt < 3; nt++) {
        int k = nt * 4 + tg;
        if (k < 9) {
            float by0 = b_off[2 * k];
            float by1 = b_off[2 * k + 1];
            int hw0 = (m0 & 4095) + wm * 16 + g;
            make_tab(b, hw0,     k, acc[nt][0] + by0, acc[nt][1] + by1);
            make_tab(b, hw0 + 8, k, acc[nt][2] + by0, acc[nt][3] + by1);
        }
    }
}

// ---------------- kernel: pipelined channel-vector gather (1 pixel/warp) ---
__global__ void __launch_bounds__(256) gather_A_kernel() {
    const int lane = threadIdx.x & 31;
    const int wid  = threadIdx.x >> 5;
    const int m = (blockIdx.x << 3) + wid;
    const int b = m >> 12;
    const __half* basep = g_xTp + (size_t)b * PP * CI;
    __half* dstm = g_A + (size_t)m * KD + lane * 8;

    ushort4 gi = g_tidx[m];
    uint4 wq   = g_tw2[m];
    uint4 a0 = __ldg((const uint4*)(basep + (int)gi.x * CI) + lane);
    uint4 a1 = __ldg((const uint4*)(basep + (int)gi.y * CI) + lane);
    uint4 a2 = __ldg((const uint4*)(basep + (int)gi.z * CI) + lane);
    uint4 a3 = __ldg((const uint4*)(basep + (int)gi.w * CI) + lane);

#pragma unroll
    for (int tap = 0; tap < 9; tap++) {
        uint4 n0, n1, n2, n3, wqn;
        if (tap < 8) {
            int idx = ((tap + 1) << 14) + m;
            ushort4 gin = g_tidx[idx];
            wqn = g_tw2[idx];
            n0 = __ldg((const uint4*)(basep + (int)gin.x * CI) + lane);
            n1 = __ldg((const uint4*)(basep + (int)gin.y * CI) + lane);
            n2 = __ldg((const uint4*)(basep + (int)gin.z * CI) + lane);
            n3 = __ldg((const uint4*)(basep + (int)gin.w * CI) + lane);
        }
        __half2 w0 = *(__half2*)&wq.x, w1 = *(__half2*)&wq.y;
        __half2 w2 = *(__half2*)&wq.z, w3 = *(__half2*)&wq.w;
        uint4 o;
        o.x = h2dot(a0.x, a1.x, a2.x, a3.x, w0, w1, w2, w3);
        o.y = h2dot(a0.y, a1.y, a2.y, a3.y, w0, w1, w2, w3);
        o.z = h2dot(a0.z, a1.z, a2.z, a3.z, w0, w1, w2, w3);
        o.w = h2dot(a0.w, a1.w, a2.w, a3.w, w0, w1, w2, w3);
        *(uint4*)(dstm + tap * 256) = o;
        if (tap < 8) {
            a0 = n0; a1 = n1; a2 = n2; a3 = n3; wq = wqn;
        }
    }
}

// ---------------- kernel: pipelined fp16 HMMA GEMM (KC=64, R11 config) -----
#define ST_A 16384
#define ST_B 16384
#define OFF_A 0
#define OFF_B (3 * ST_A)
#define SMEM_GEMM (3 * ST_A + 3 * ST_B)     // 98304

__global__ void __launch_bounds__(256, 2)
gemm_main() {
    extern __shared__ char smem[];
    const uint32_t sb = smem_u32(smem);
    const int tid  = threadIdx.x;
    const int lane = tid & 31;
    const int wid  = tid >> 5;
    const int g  = lane >> 2;
    const int tg = lane & 3;
    const int wm = wid & 3;
    const int wn = wid >> 2;
    const int m0 = blockIdx.x << 7;
    const int by = blockIdx.y;
    const int b  = m0 >> 12;

    const int cm   = tid & 127;
    const int ckl0 = tid >> 7;

    auto issue = [&](int kt, int s) {
        const __half* arow = g_A + (size_t)(m0 + cm) * KD + kt * 64;
#pragma unroll
        for (int sub = 0; sub < 2; sub++) {
#pragma unroll
            for (int q = 0; q < 2; q++) {
                int ckl = ckl0 + q * 2;
                uint32_t dstA = (uint32_t)(sub * 8192 + (cm >> 1) * 128
                             + (((((cm & 1) << 2) + ckl) ^ ((cm >> 1) & 7)) << 4));
                cp_async16(sb + OFF_A + s * ST_A + dstA, arow + sub * 32 + ckl * 8);
            }
        }
        const float4* wb4 = (const float4*)g_wB;
#pragma unroll
        for (int r = 0; r < 4; r++) {
            int idx = r * 256 + tid;
            int sub = idx >> 9;
            int i2  = idx & 511;
            int k16 = i2 >> 8;
            int npl = (i2 >> 5) & 7;
            int ln  = i2 & 31;
            cp_async16(sb + OFF_B + s * ST_B + idx * 16,
                       wb4 + (size_t)(2 * kt + sub) * 1024 + k16 * 512
                           + (8 * by + npl) * 32 + ln);
        }
        asm volatile("cp.async.commit_group;" ::: "memory");
    };

    float acc[2][8][4];
#pragma unroll
    for (int mt = 0; mt < 2; mt++)
#pragma unroll
        for (int nt = 0; nt < 8; nt++)
#pragma unroll
            for (int r = 0; r < 4; r++) acc[mt][nt][r] = 0.f;

    auto compute = [&](int s) {
#pragma unroll
        for (int k32 = 0; k32 < 2; k32++) {
            const uint32_t Ab = sb + OFF_A + s * ST_A + k32 * 8192;
            const uint32_t Bb = sb + OFF_B + s * ST_B + k32 * 8192;
#pragma unroll
            for (int k16 = 0; k16 < 2; k16++) {
                uint32_t a[2][4];
#pragma unroll
                for (int mt = 0; mt < 2; mt++) {
                    int mr = wm * 32 + mt * 16;
                    int t = lane >> 3, r = lane & 7;
                    int mrow = mr + ((t & 1) << 3) + r;
                    int rp = mrow >> 1;
                    int cc = ((mrow & 1) << 2) + (k16 << 1) + (t >> 1);
                    uint32_t addr = Ab + rp * 128 + ((cc ^ (rp & 7)) << 4);
                    asm volatile(
                        "ldmatrix.sync.aligned.m8n8.x4.shared.b16 {%0,%1,%2,%3}, [%4];"
                        : "=r"(a[mt][0]), "=r"(a[mt][1]), "=r"(a[mt][2]), "=r"(a[mt][3])
                        : "r"(addr));
                }
#pragma unroll
                for (int j = 0; j < 4; j++) {
                    uint32_t b0, b1, b2, b3;
                    uint32_t addr = Bb + (((k16 * 8) + wn * 4 + j) * 32 + lane) * 16;
                    asm volatile("ld.shared.v4.u32 {%0,%1,%2,%3}, [%4];"
                                 : "=r"(b0), "=r"(b1), "=r"(b2), "=r"(b3) : "r"(addr));
                    mma_f16(acc[0][2 * j],     a[0], b0, b1);
                    mma_f16(acc[1][2 * j],     a[1], b0, b1);
                    mma_f16(acc[0][2 * j + 1], a[0], b2, b3);
                    mma_f16(acc[1][2 * j + 1], a[1], b2, b3);
                }
            }
        }
    };

    issue(0, 0);
    issue(1, 1);
    asm volatile("cp.async.wait_group 1;" ::: "memory");
    __syncthreads();

#pragma unroll 1
    for (int it = 0; it < NKT2 / 3; it++) {
        int kt = it * 3;
        compute(0);
        if (kt + 2 < NKT2) {
            issue(kt + 2, 2);
            asm volatile("cp.async.wait_group 1;" ::: "memory");
        } else {
            asm volatile("cp.async.wait_group 0;" ::: "memory");
        }
        __syncthreads();
        compute(1);
        if (kt + 3 < NKT2) {
            issue(kt + 3, 0);
            asm volatile("cp.async.wait_group 1;" ::: "memory");
        } else {
            asm volatile("cp.async.wait_group 0;" ::: "memory");
        }
        __syncthreads();
        compute(2);
        if (kt + 4 < NKT2) {
            issue(kt + 4, 1);
            asm volatile("cp.async.wait_group 1;" ::: "memory");
        } else {
            asm volatile("cp.async.wait_group 0;" ::: "memory");
        }
        __syncthreads();
    }

    const int hwb = (m0 & 4095);
#pragma unroll
    for (int nt = 0; nt < 8; nt++) {
        int n = by * 128 + wn * 64 + nt * 8 + 2 * tg;
        __half* p0 = g_rawh + ((size_t)(b * CO + n) << 12);
        __half* p1 = p0 + HW;
        float s0 = 0.f, q0 = 0.f, s1 = 0.f, q1 = 0.f;
#pragma unroll
        for (int mt = 0; mt < 2; mt++) {
            int hw0 = hwb + wm * 32 + mt * 16 + g;
            float d0 = acc[mt][nt][0], d1 = acc[mt][nt][1];
            float d2 = acc[mt][nt][2], d3 = acc[mt][nt][3];
            p0[hw0]     = __float2half(d0);
            p1[hw0]     = __float2half(d1);
            p0[hw0 + 8] = __float2half(d2);
            p1[hw0 + 8] = __float2half(d3);
            s0 += d0 + d2;  q0 += d0 * d0 + d2 * d2;
            s1 += d1 + d3;  q1 += d1 * d1 + d3 * d3;
        }
#pragma unroll
        for (int o = 4; o < 32; o <<= 1) {
            s0 += __shfl_xor_sync(0xFFFFFFFF, s0, o);
            q0 += __shfl_xor_sync(0xFFFFFFFF, q0, o);
            s1 += __shfl_xor_sync(0xFFFFFFFF, s1, o);
            q1 += __shfl_xor_sync(0xFFFFFFFF, q1, o);
        }
        if (lane < 4) {
            atomicAdd(&g_sum[n], s0);
            atomicAdd(&g_sum2[n], q0);
            atomicAdd(&g_sum[n + 1], s1);
            atomicAdd(&g_sum2[n + 1], q1);
        }
    }
}

// ---------------- BN finalize + apply (fused, fp16 raw) ---------------------
__global__ void bn_apply(float* __restrict__ out,
                         const float* __restrict__ gamma,
                         const float* __restrict__ beta) {
    __shared__ float ssc[256], ssh[256];
    int t = threadIdx.x;
    {
        float mean = g_sum[t] * (1.f / 16384.f);
        float var  = g_sum2[t] * (1.f / 16384.f) - mean * mean;
        float inv  = gamma[t] * rsqrtf(var + 1e-5f);
        ssc[t] = inv;
        ssh[t] = beta[t] - mean * inv;
    }
    __syncthreads();
    int i = blockIdx.x * 256 + t;           // uint4-of-half index (8 elems)
    int o = (i >> 9) & 255;
    uint4 v = ((const uint4*)g_rawh)[i];
    float sc = ssc[o], sf = ssh[o];
    float2 f0 = __half22float2(*(__half2*)&v.x);
    float2 f1 = __half22float2(*(__half2*)&v.y);
    float2 f2 = __half22float2(*(__half2*)&v.z);
    float2 f3 = __half22float2(*(__half2*)&v.w);
    float4 q0, q1;
    q0.x = fmaxf(f0.x * sc + sf, 0.f);
    q0.y = fmaxf(f0.y * sc + sf, 0.f);
    q0.z = fmaxf(f1.x * sc + sf, 0.f);
    q0.w = fmaxf(f1.y * sc + sf, 0.f);
    q1.x = fmaxf(f2.x * sc + sf, 0.f);
    q1.y = fmaxf(f2.y * sc + sf, 0.f);
    q1.z = fmaxf(f3.x * sc + sf, 0.f);
    q1.w = fmaxf(f3.y * sc + sf, 0.f);
    ((float4*)out)[2 * i]     = q0;
    ((float4*)out)[2 * i + 1] = q1;
}

// ---------------- launch ----------------
extern "C" void kernel_launch(void* const* d_in, const int* in_sizes, int n_in,
                              void* d_out, int out_size) {
    const float* x      = (const float*)d_in[0];
    const float* w_off  = (const float*)d_in[1];
    const float* b_off  = (const float*)d_in[2];
    const float* w_conv = (const float*)d_in[3];
    const float* gamma  = (const float*)d_in[4];
    const float* beta   = (const float*)d_in[5];
    float* out = (float*)d_out;

    cudaFuncSetAttribute(gemm_main,
                         cudaFuncAttributeMaxDynamicSharedMemorySize, SMEM_GEMM);

    prep_all<<<NB_PREP, 256>>>(x, w_conv, w_off);
    offset_gemm<<<MTOT / 64, 128>>>(b_off);
    gather_A_kernel<<<MTOT / 8, 256>>>();
    gemm_main<<<dim3(MTOT / 128, 2), 256, SMEM_GEMM>>>();
    bn_apply<<<(BB * CO * HW / 8) / 256, 256>>>(out, gamma, beta);
}

// round 17
// speedup vs baseline: 1.0447x; 1.0160x over previous
#include <cuda_runtime.h>
#include <cuda_fp16.h>
#include <cstdint>

#define BB 4
#define CI 256
#define CO 256
#define HH 64
#define WW 64
#define HW 4096
#define KD 2304          // CI * 9
#define MTOT 16384
#define NCHUNK 72        // KD / 32  (B packing granularity)
#define NKT2 36          // KD / 64  (gemm main-loop chunks)
#define PP 4356          // 66*66 padded pixels

// ---------------- scratch ----------------
__device__ __align__(16) uint32_t g_wB[NCHUNK * 4096];     // frag-ordered fp16 B (main, tap-major k)
__device__ __align__(16) uint32_t g_wOffB[NCHUNK * 384];   // frag-ordered fp16 B (offset)
__device__ __align__(16) __half g_A[(size_t)MTOT * KD];    // sampled A fp16, [m][2304]
__device__ __align__(16) __half g_xTp[BB * PP * CI];       // fp16 x, padded transposed (hw, c)
__device__ __align__(16) ushort4 g_tidx[9 * MTOT];         // corner PADDED row indices
__device__ __align__(16) uint4   g_tw2[9 * MTOT];          // corner weights as 4x half2
__device__ __align__(16) float g_raw[BB * CO * HW];        // pre-BN output (fp32)
__device__ float g_sum[CO];
__device__ float g_sum2[CO];

// ---------------- helpers ----------------
__device__ __forceinline__ uint32_t smem_u32(const void* p) {
    uint32_t a;
    asm("{ .reg .u64 t; cvta.to.shared.u64 t, %1; cvt.u32.u64 %0, t; }" : "=r"(a) : "l"(p));
    return a;
}
__device__ __forceinline__ uint32_t pack_h2(float lo, float hi) {
    __half2 h = __floats2half2_rn(lo, hi);
    return *(uint32_t*)&h;
}
__device__ __forceinline__ void mma_f16(float* d, const uint32_t* a,
                                        uint32_t b0, uint32_t b1) {
    asm volatile(
        "mma.sync.aligned.m16n8k16.row.col.f32.f16.f16.f32 "
        "{%0,%1,%2,%3}, {%4,%5,%6,%7}, {%8,%9}, {%0,%1,%2,%3};"
        : "+f"(d[0]), "+f"(d[1]), "+f"(d[2]), "+f"(d[3])
        : "r"(a[0]), "r"(a[1]), "r"(a[2]), "r"(a[3]), "r"(b0), "r"(b1));
}
__device__ __forceinline__ void cp_async16(uint32_t saddr, const void* gaddr) {
    asm volatile("cp.async.cg.shared.global [%0], [%1], 16;" :: "r"(saddr), "l"(gaddr));
}
__device__ __forceinline__ uint32_t h2dot(uint32_t c0, uint32_t c1, uint32_t c2, uint32_t c3,
                                          __half2 w0, __half2 w1, __half2 w2, __half2 w3) {
    __half2 r = __hmul2(w0, *(__half2*)&c0);
    r = __hfma2(w1, *(__half2*)&c1, r);
    r = __hfma2(w2, *(__half2*)&c2, r);
    r = __hfma2(w3, *(__half2*)&c3, r);
    return *(uint32_t*)&r;
}

// bilinear table construction for one (pixel, tap)
__device__ __forceinline__ void make_tab(int b, int hw, int k, float offy, float offx) {
    int h = hw >> 6, w = hw & 63;
    int k3 = k / 3;
    float py = (float)(h + k3 - 1) + offy;
    float px = (float)(w + (k - k3 * 3) - 1) + offx;
    float fy0 = floorf(py), fx0 = floorf(px);
    float wy1 = py - fy0, wx1 = px - fx0;
    float wy0 = 1.f - wy1, wx0 = 1.f - wx1;
    int iy0 = (int)fy0, ix0 = (int)fx0;
    int iy1 = iy0 + 1, ix1 = ix0 + 1;
    float vy0 = (iy0 >= 0 && iy0 < HH) ? 1.f : 0.f;
    float vy1 = (iy1 >= 0 && iy1 < HH) ? 1.f : 0.f;
    float vx0 = (ix0 >= 0 && ix0 < WW) ? 1.f : 0.f;
    float vx1 = (ix1 >= 0 && ix1 < WW) ? 1.f : 0.f;
    int cy0 = min(max(iy0, 0), HH - 1), cy1 = min(max(iy1, 0), HH - 1);
    int cx0 = min(max(ix0, 0), WW - 1), cx1 = min(max(ix1, 0), WW - 1);
    ushort4 gi;
    gi.x = (unsigned short)((cy0 + 1) * 66 + cx0 + 1);
    gi.y = (unsigned short)((cy0 + 1) * 66 + cx1 + 1);
    gi.z = (unsigned short)((cy1 + 1) * 66 + cx0 + 1);
    gi.w = (unsigned short)((cy1 + 1) * 66 + cx1 + 1);
    int idx = (k << 14) + (b << 12) + hw;
    g_tidx[idx] = gi;
    float w00 = wy0 * wx0 * vy0 * vx0;
    float w01 = wy0 * wx1 * vy0 * vx1;
    float w10 = wy1 * wx0 * vy1 * vx0;
    float w11 = wy1 * wx1 * vy1 * vx1;
    uint4 wq;
    wq.x = pack_h2(w00, w00);
    wq.y = pack_h2(w01, w01);
    wq.z = pack_h2(w10, w10);
    wq.w = pack_h2(w11, w11);
    g_tw2[idx] = wq;
}

// ---------------- kernel: unified prep (xhT + wB + pad + wOffB + stats) ----
#define N_WB   (NCHUNK * 4096)
#define N_PAD  (BB * 260 * 32)
#define N_WOFF (NCHUNK * 384)
#define N_MISC (N_WB + N_PAD + N_WOFF + 256)    // 356096 = 1391*256
#define NB_XHT (BB * HH * 4)                    // 1024 transpose blocks
#define NB_PREP (NB_XHT + N_MISC / 256)         // 2415

__global__ void prep_all(const float* __restrict__ x,
                         const float* __restrict__ w_conv,
                         const float* __restrict__ w_off) {
    __shared__ float tile[64][65];
    int blk = blockIdx.x;
    int t = threadIdx.x;
    if (blk < NB_XHT) {
        int bh = blk & 255;
        int c0 = (blk >> 8) * 64;
        int b = bh >> 6, h = bh & 63;
        int ci = t >> 6, w = t & 63;
#pragma unroll
        for (int rep = 0; rep < 16; rep++) {
            int c = c0 + ci + rep * 4;
            tile[ci + rep * 4][w] = x[((size_t)(b * CI + c) << 12) + h * 64 + w];
        }
        __syncthreads();
#pragma unroll
        for (int rep = 0; rep < 2; rep++) {
            int e = t + rep * 256;
            int w2 = e & 63, q = e >> 6;
            __half hv[8];
#pragma unroll
            for (int j = 0; j < 8; j++) hv[j] = __float2half(tile[q * 8 + j][w2]);
            size_t dst = ((size_t)b * PP + (h + 1) * 66 + (w2 + 1)) * CI + c0 + q * 8;
            *(uint4*)(g_xTp + dst) = *(uint4*)hv;
        }
        return;
    }
    int idx = (blk - NB_XHT) * 256 + t;
    if (idx < N_WB) {
        int kt = idx >> 12;
        int r  = idx & 4095;
        int k16  = r >> 11;
        int np   = (r >> 7) & 15;
        int lane = (r >> 2) & 31;
        int w    = r & 3;
        int g = lane >> 2, tg = lane & 3;
        int nt = np * 2 + (w >> 1);
        int h  = w & 1;
        int n  = nt * 8 + g;
        int ck = kt * 32 + k16 * 16 + h * 8 + 2 * tg;   // tap-major k index
        int tap = ck >> 8;
        int c   = ck & 255;
        g_wB[idx] = pack_h2(w_conv[n * KD + c * 9 + tap],
                            w_conv[n * KD + (c + 1) * 9 + tap]);
        return;
    }
    idx -= N_WB;
    if (idx < N_PAD) {
        int q = idx & 31;
        int r = (idx >> 5) % 260;
        int b = idx / (260 * 32);
        int row;
        if (r < 66)       row = r;
        else if (r < 132) row = 65 * 66 + (r - 66);
        else if (r < 196) row = (r - 132 + 1) * 66;
        else              row = (r - 196 + 1) * 66 + 65;
        ((uint4*)(g_xTp + ((size_t)b * PP + row) * CI))[q] = make_uint4(0, 0, 0, 0);
        return;
    }
    idx -= N_PAD;
    if (idx < N_WOFF) {
        int kt = idx / 384;
        int r  = idx - kt * 384;
        int k16  = r / 192;
        int nt   = (r / 64) % 3;
        int lane = (r >> 1) & 31;
        int h    = r & 1;
        int g = lane >> 2, tg = lane & 3;
        int n = nt * 8 + g;
        int tap = kt >> 3;
        int c = (kt & 7) * 32 + k16 * 16 + h * 8 + 2 * tg;
        uint32_t val = 0;
        if (n < 18)
            val = pack_h2(w_off[n * KD + c * 9 + tap], w_off[n * KD + (c + 1) * 9 + tap]);
        g_wOffB[idx] = val;
        return;
    }
    idx -= N_WOFF;
    if (idx < 256) {
        g_sum[idx] = 0.f;
        g_sum2[idx] = 0.f;
    }
}

// ---------------- kernel: offset conv GEMM + fused bilinear tables ---------
__global__ void __launch_bounds__(128)
offset_gemm(const float* __restrict__ b_off) {
    __shared__ __align__(16) char As[3 * 4096];
    __shared__ __align__(16) char Bs[3 * 1536];
    const uint32_t Ab0 = smem_u32(As);
    const uint32_t Bb0 = smem_u32(Bs);
    const int t = threadIdx.x;
    const int lane = t & 31;
    const int wm = t >> 5;
    const int g = lane >> 2;
    const int tg = lane & 3;
    const int m0 = blockIdx.x << 6;
    const int b  = m0 >> 12;

    const int ar = t & 63;
    const int part = t >> 6;
    const int hw_a = (m0 + ar) & 4095;
    const int prow = ((hw_a >> 6) + 1) * 66 + (hw_a & 63) + 1;
    const __half* arow = g_xTp + ((size_t)b * PP + prow) * CI;
    const int rp = ar >> 1;
    const uint32_t dstA_base = rp * 128;

    auto issue = [&](int kt, int s) {
        int tap = kt >> 3;
        int shift = (tap / 3 - 1) * 66 + (tap % 3 - 1);
        const __half* src = arow + (size_t)shift * CI + (kt & 7) * 32;
#pragma unroll
        for (int qq = 0; qq < 2; qq++) {
            int q = part * 2 + qq;
            uint32_t cc = ((ar & 1) << 2) + q;
            cp_async16(Ab0 + s * 4096 + dstA_base + ((cc ^ (rp & 7)) << 4), src + q * 8);
        }
        if (t < 96)
            cp_async16(Bb0 + s * 1536 + t * 16, g_wOffB + kt * 384 + t * 4);
        asm volatile("cp.async.commit_group;" ::: "memory");
    };

    float acc[3][4];
#pragma unroll
    for (int nt = 0; nt < 3; nt++)
#pragma unroll
        for (int r = 0; r < 4; r++) acc[nt][r] = 0.f;

    auto compute = [&](int s) {
        const uint32_t Ab = Ab0 + s * 4096;
        const uint32_t Bb = Bb0 + s * 1536;
#pragma unroll
        for (int k16 = 0; k16 < 2; k16++) {
            uint32_t a[4];
            {
                int mr = wm * 16;
                int tt = lane >> 3, r = lane & 7;
                int mrow = mr + ((tt & 1) << 3) + r;
                int rp2 = mrow >> 1;
                int cc = ((mrow & 1) << 2) + (k16 << 1) + (tt >> 1);
                uint32_t addr = Ab + rp2 * 128 + ((cc ^ (rp2 & 7)) << 4);
                asm volatile(
                    "ldmatrix.sync.aligned.m8n8.x4.shared.b16 {%0,%1,%2,%3}, [%4];"
                    : "=r"(a[0]), "=r"(a[1]), "=r"(a[2]), "=r"(a[3])
                    : "r"(addr));
            }
#pragma unroll
            for (int nt = 0; nt < 3; nt++) {
                uint32_t b0, b1;
                uint32_t addr = Bb + ((k16 * 3 + nt) * 64 + lane * 2) * 4;
                asm volatile("ld.shared.v2.u32 {%0,%1}, [%2];"
                             : "=r"(b0), "=r"(b1) : "r"(addr));
                mma_f16(acc[nt], a, b0, b1);
            }
        }
    };

    issue(0, 0);
    issue(1, 1);
    asm volatile("cp.async.wait_group 1;" ::: "memory");
    __syncthreads();

#pragma unroll 1
    for (int it = 0; it < NCHUNK / 3; it++) {
        int kt = it * 3;
        compute(0);
        if (kt + 2 < NCHUNK) {
            issue(kt + 2, 2);
            asm volatile("cp.async.wait_group 1;" ::: "memory");
        } else {
            asm volatile("cp.async.wait_group 0;" ::: "memory");
        }
        __syncthreads();
        compute(1);
        if (kt + 3 < NCHUNK) {
            issue(kt + 3, 0);
            asm volatile("cp.async.wait_group 1;" ::: "memory");
        } else {
            asm volatile("cp.async.wait_group 0;" ::: "memory");
        }
        __syncthreads();
        compute(2);
        if (kt + 4 < NCHUNK) {
            issue(kt + 4, 1);
            asm volatile("cp.async.wait_group 1;" ::: "memory");
        } else {
            asm volatile("cp.async.wait_group 0;" ::: "memory");
        }
        __syncthreads();
    }

#pragma unroll
    for (int nt = 0; nt < 3; nt++) {
        int k = nt * 4 + tg;
        if (k < 9) {
            float by0 = b_off[2 * k];
            float by1 = b_off[2 * k + 1];
            int hw0 = (m0 & 4095) + wm * 16 + g;
            make_tab(b, hw0,     k, acc[nt][0] + by0, acc[nt][1] + by1);
            make_tab(b, hw0 + 8, k, acc[nt][2] + by0, acc[nt][3] + by1);
        }
    }
}

// ---------------- kernel: depth-2 pipelined channel-vector gather ----------
// warp = one pixel m; tap t+1 and t+2 loads in flight while computing tap t.
__global__ void __launch_bounds__(256) gather_A_kernel() {
    const int lane = threadIdx.x & 31;
    const int wid  = threadIdx.x >> 5;
    const int m = (blockIdx.x << 3) + wid;
    const int b = m >> 12;
    const __half* basep = g_xTp + (size_t)b * PP * CI;
    __half* dstm = g_A + (size_t)m * KD + lane * 8;

    uint4 cor[2][4];
    uint4 wq[2];

#pragma unroll
    for (int s = 0; s < 2; s++) {
        int idx = (s << 14) + m;
        ushort4 gi = g_tidx[idx];
        wq[s] = g_tw2[idx];
        cor[s][0] = __ldg((const uint4*)(basep + (int)gi.x * CI) + lane);
        cor[s][1] = __ldg((const uint4*)(basep + (int)gi.y * CI) + lane);
        cor[s][2] = __ldg((const uint4*)(basep + (int)gi.z * CI) + lane);
        cor[s][3] = __ldg((const uint4*)(basep + (int)gi.w * CI) + lane);
    }

#pragma unroll
    for (int tap = 0; tap < 9; tap++) {
        const int s = tap & 1;
        __half2 w0 = *(__half2*)&wq[s].x, w1 = *(__half2*)&wq[s].y;
        __half2 w2 = *(__half2*)&wq[s].z, w3 = *(__half2*)&wq[s].w;
        uint4 o;
        o.x = h2dot(cor[s][0].x, cor[s][1].x, cor[s][2].x, cor[s][3].x, w0, w1, w2, w3);
        o.y = h2dot(cor[s][0].y, cor[s][1].y, cor[s][2].y, cor[s][3].y, w0, w1, w2, w3);
        o.z = h2dot(cor[s][0].z, cor[s][1].z, cor[s][2].z, cor[s][3].z, w0, w1, w2, w3);
        o.w = h2dot(cor[s][0].w, cor[s][1].w, cor[s][2].w, cor[s][3].w, w0, w1, w2, w3);
        *(uint4*)(dstm + tap * 256) = o;
        if (tap + 2 < 9) {
            int idx = ((tap + 2) << 14) + m;
            ushort4 gi = g_tidx[idx];
            wq[s] = g_tw2[idx];
            cor[s][0] = __ldg((const uint4*)(basep + (int)gi.x * CI) + lane);
            cor[s][1] = __ldg((const uint4*)(basep + (int)gi.y * CI) + lane);
            cor[s][2] = __ldg((const uint4*)(basep + (int)gi.z * CI) + lane);
            cor[s][3] = __ldg((const uint4*)(basep + (int)gi.w * CI) + lane);
        }
    }
}

// ---------------- kernel: pipelined fp16 HMMA GEMM (KC=64, R11 config) -----
#define ST_A 16384
#define ST_B 16384
#define OFF_A 0
#define OFF_B (3 * ST_A)
#define SMEM_GEMM (3 * ST_A + 3 * ST_B)     // 98304

__global__ void __launch_bounds__(256, 2)
gemm_main() {
    extern __shared__ char smem[];
    const uint32_t sb = smem_u32(smem);
    const int tid  = threadIdx.x;
    const int lane = tid & 31;
    const int wid  = tid >> 5;
    const int g  = lane >> 2;
    const int tg = lane & 3;
    const int wm = wid & 3;
    const int wn = wid >> 2;
    const int m0 = blockIdx.x << 7;
    const int by = blockIdx.y;
    const int b  = m0 >> 12;

    const int cm   = tid & 127;
    const int ckl0 = tid >> 7;

    auto issue = [&](int kt, int s) {
        const __half* arow = g_A + (size_t)(m0 + cm) * KD + kt * 64;
#pragma unroll
        for (int sub = 0; sub < 2; sub++) {
#pragma unroll
            for (int q = 0; q < 2; q++) {
                int ckl = ckl0 + q * 2;
                uint32_t dstA = (uint32_t)(sub * 8192 + (cm >> 1) * 128
                             + (((((cm & 1) << 2) + ckl) ^ ((cm >> 1) & 7)) << 4));
                cp_async16(sb + OFF_A + s * ST_A + dstA, arow + sub * 32 + ckl * 8);
            }
        }
        const float4* wb4 = (const float4*)g_wB;
#pragma unroll
        for (int r = 0; r < 4; r++) {
            int idx = r * 256 + tid;
            int sub = idx >> 9;
            int i2  = idx & 511;
            int k16 = i2 >> 8;
            int npl = (i2 >> 5) & 7;
            int ln  = i2 & 31;
            cp_async16(sb + OFF_B + s * ST_B + idx * 16,
                       wb4 + (size_t)(2 * kt + sub) * 1024 + k16 * 512
                           + (8 * by + npl) * 32 + ln);
        }
        asm volatile("cp.async.commit_group;" ::: "memory");
    };

    float acc[2][8][4];
#pragma unroll
    for (int mt = 0; mt < 2; mt++)
#pragma unroll
        for (int nt = 0; nt < 8; nt++)
#pragma unroll
            for (int r = 0; r < 4; r++) acc[mt][nt][r] = 0.f;

    auto compute = [&](int s) {
#pragma unroll
        for (int k32 = 0; k32 < 2; k32++) {
            const uint32_t Ab = sb + OFF_A + s * ST_A + k32 * 8192;
            const uint32_t Bb = sb + OFF_B + s * ST_B + k32 * 8192;
#pragma unroll
            for (int k16 = 0; k16 < 2; k16++) {
                uint32_t a[2][4];
#pragma unroll
                for (int mt = 0; mt < 2; mt++) {
                    int mr = wm * 32 + mt * 16;
                    int t = lane >> 3, r = lane & 7;
                    int mrow = mr + ((t & 1) << 3) + r;
                    int rp = mrow >> 1;
                    int cc = ((mrow & 1) << 2) + (k16 << 1) + (t >> 1);
                    uint32_t addr = Ab + rp * 128 + ((cc ^ (rp & 7)) << 4);
                    asm volatile(
                        "ldmatrix.sync.aligned.m8n8.x4.shared.b16 {%0,%1,%2,%3}, [%4];"
                        : "=r"(a[mt][0]), "=r"(a[mt][1]), "=r"(a[mt][2]), "=r"(a[mt][3])
                        : "r"(addr));
                }
#pragma unroll
                for (int j = 0; j < 4; j++) {
                    uint32_t b0, b1, b2, b3;
                    uint32_t addr = Bb + (((k16 * 8) + wn * 4 + j) * 32 + lane) * 16;
                    asm volatile("ld.shared.v4.u32 {%0,%1,%2,%3}, [%4];"
                                 : "=r"(b0), "=r"(b1), "=r"(b2), "=r"(b3) : "r"(addr));
                    mma_f16(acc[0][2 * j],     a[0], b0, b1);
                    mma_f16(acc[1][2 * j],     a[1], b0, b1);
                    mma_f16(acc[0][2 * j + 1], a[0], b2, b3);
                    mma_f16(acc[1][2 * j + 1], a[1], b2, b3);
                }
            }
        }
    };

    issue(0, 0);
    issue(1, 1);
    asm volatile("cp.async.wait_group 1;" ::: "memory");
    __syncthreads();

#pragma unroll 1
    for (int it = 0; it < NKT2 / 3; it++) {
        int kt = it * 3;
        compute(0);
        if (kt + 2 < NKT2) {
            issue(kt + 2, 2);
            asm volatile("cp.async.wait_group 1;" ::: "memory");
        } else {
            asm volatile("cp.async.wait_group 0;" ::: "memory");
        }
        __syncthreads();
        compute(1);
        if (kt + 3 < NKT2) {
            issue(kt + 3, 0);
            asm volatile("cp.async.wait_group 1;" ::: "memory");
        } else {
            asm volatile("cp.async.wait_group 0;" ::: "memory");
        }
        __syncthreads();
        compute(2);
        if (kt + 4 < NKT2) {
            issue(kt + 4, 1);
            asm volatile("cp.async.wait_group 1;" ::: "memory");
        } else {
            asm volatile("cp.async.wait_group 0;" ::: "memory");
        }
        __syncthreads();
    }

    const int hwb = (m0 & 4095);
#pragma unroll
    for (int nt = 0; nt < 8; nt++) {
        int n = by * 128 + wn * 64 + nt * 8 + 2 * tg;
        float* p0 = g_raw + ((size_t)(b * CO + n) << 12);
        float* p1 = p0 + HW;
        float s0 = 0.f, q0 = 0.f, s1 = 0.f, q1 = 0.f;
#pragma unroll
        for (int mt = 0; mt < 2; mt++) {
            int hw0 = hwb + wm * 32 + mt * 16 + g;
            float d0 = acc[mt][nt][0], d1 = acc[mt][nt][1];
            float d2 = acc[mt][nt][2], d3 = acc[mt][nt][3];
            p0[hw0]     = d0;
            p1[hw0]     = d1;
            p0[hw0 + 8] = d2;
            p1[hw0 + 8] = d3;
            s0 += d0 + d2;  q0 += d0 * d0 + d2 * d2;
            s1 += d1 + d3;  q1 += d1 * d1 + d3 * d3;
        }
#pragma unroll
        for (int o = 4; o < 32; o <<= 1) {
            s0 += __shfl_xor_sync(0xFFFFFFFF, s0, o);
            q0 += __shfl_xor_sync(0xFFFFFFFF, q0, o);
            s1 += __shfl_xor_sync(0xFFFFFFFF, s1, o);
            q1 += __shfl_xor_sync(0xFFFFFFFF, q1, o);
        }
        if (lane < 4) {
            atomicAdd(&g_sum[n], s0);
            atomicAdd(&g_sum2[n], q0);
            atomicAdd(&g_sum[n + 1], s1);
            atomicAdd(&g_sum2[n + 1], q1);
        }
    }
}

// ---------------- BN finalize + apply (fused, fp32 raw) ---------------------
__global__ void bn_apply(float* __restrict__ out,
                         const float* __restrict__ gamma,
                         const float* __restrict__ beta) {
    __shared__ float ssc[256], ssh[256];
    int t = threadIdx.x;
    {
        float mean = g_sum[t] * (1.f / 16384.f);
        float var  = g_sum2[t] * (1.f / 16384.f) - mean * mean;
        float inv  = gamma[t] * rsqrtf(var + 1e-5f);
        ssc[t] = inv;
        ssh[t] = beta[t] - mean * inv;
    }
    __syncthreads();
    int base = blockIdx.x * 1024;
#pragma unroll
    for (int r = 0; r < 4; r++) {
        int i = base + r * 256 + t;
        int o = (i >> 10) & 255;
        float4 v = ((const float4*)g_raw)[i];
        float sc = ssc[o], sf = ssh[o];
        float4 q;
        q.x = fmaxf(v.x * sc + sf, 0.f);
        q.y = fmaxf(v.y * sc + sf, 0.f);
        q.z = fmaxf(v.z * sc + sf, 0.f);
        q.w = fmaxf(v.w * sc + sf, 0.f);
        ((float4*)out)[i] = q;
    }
}

// ---------------- launch ----------------
extern "C" void kernel_launch(void* const* d_in, const int* in_sizes, int n_in,
                              void* d_out, int out_size) {
    const float* x      = (const float*)d_in[0];
    const float* w_off  = (const float*)d_in[1];
    const float* b_off  = (const float*)d_in[2];
    const float* w_conv = (const float*)d_in[3];
    const float* gamma  = (const float*)d_in[4];
    const float* beta   = (const float*)d_in[5];
    float* out = (float*)d_out;

    cudaFuncSetAttribute(gemm_main,
                         cudaFuncAttributeMaxDynamicSharedMemorySize, SMEM_GEMM);

    prep_all<<<NB_PREP, 256>>>(x, w_conv, w_off);
    offset_gemm<<<MTOT / 64, 128>>>(b_off);
    gather_A_kernel<<<MTOT / 8, 256>>>();
    gemm_main<<<dim3(MTOT / 128, 2), 256, SMEM_GEMM>>>();
    bn_apply<<<(BB * CO * HW / 4) / 1024, 256>>>(out, gamma, beta);
}